// round 13
// baseline (speedup 1.0000x reference)
#include <cuda_runtime.h>
#include <cuda_bf16.h>
#include <cstdint>

#define NB    16384
#define DD    1024
#define EPSF  1e-8f
#define TM    128                     // CTA rows
#define TNC   256                     // CTA cols
#define KCH   64                      // k elems per smem stage
#define NSTG  (DD / KCH)              // 16 stages
#define LDS_  72                      // smem row stride in bf16 (144 B)
#define ABUF  (TM * LDS_ * 2)         // 18432 B per A buffer
#define BBUF  (TNC * LDS_ * 2)        // 36864 B per B buffer
#define STG_B (ABUF + BBUF)           // 55296 B per stage
#define SMEM_DYN (2 * STG_B)          // 110592 B

// ---------------- device scratch (allocation-free rule) ------------------------
__device__ __nv_bfloat16       g_xbf[(size_t)NB * DD];   // 32 MB bf16 normalized
__device__ float               g_inv[NB];                // per-row 1/||x||
__device__ unsigned long long  g_best[NB];
__device__ float               g_logs[NB];

// ---------------- helpers ------------------------------------------------------
__device__ __forceinline__ uint32_t smem_u32(const void* p) {
    uint32_t a;
    asm("{ .reg .u64 t; cvta.to.shared.u64 t, %1; cvt.u32.u64 %0, t; }" : "=r"(a) : "l"(p));
    return a;
}
__device__ __forceinline__ unsigned long long packkey(float v, int j) {
    unsigned u = __float_as_uint(v);
    u = (u & 0x80000000u) ? ~u : (u | 0x80000000u);   // total order on floats
    return ((unsigned long long)u << 32) | (unsigned)j;
}
__device__ __forceinline__ void cpasync16(uint32_t dst, const void* src) {
    asm volatile("cp.async.cg.shared.global [%0], [%1], 16;" :: "r"(dst), "l"(src) : "memory");
}
__device__ __forceinline__ void ldsm_x4(uint32_t* r, uint32_t addr) {
    asm volatile("ldmatrix.sync.aligned.m8n8.x4.shared.b16 {%0,%1,%2,%3}, [%4];"
                 : "=r"(r[0]), "=r"(r[1]), "=r"(r[2]), "=r"(r[3]) : "r"(addr));
}
__device__ __forceinline__ void mma16816(float* c, const uint32_t* a, uint32_t b0, uint32_t b1) {
    asm volatile("mma.sync.aligned.m16n8k16.row.col.f32.bf16.bf16.f32 "
                 "{%0,%1,%2,%3}, {%4,%5,%6,%7}, {%8,%9}, {%0,%1,%2,%3};"
                 : "+f"(c[0]), "+f"(c[1]), "+f"(c[2]), "+f"(c[3])
                 : "r"(a[0]), "r"(a[1]), "r"(a[2]), "r"(a[3]), "r"(b0), "r"(b1));
}

// ---------------- phase 1: normalize -> bf16 + inv-norm, reset g_best ----------
__global__ void normalize_kernel(const float* __restrict__ x) {
    int row = blockIdx.x;
    int t   = threadIdx.x;                       // 256 threads, 1 float4 each
    float4 v = ((const float4*)(x + (size_t)row * DD))[t];
    float ss = v.x*v.x + v.y*v.y + v.z*v.z + v.w*v.w;
    #pragma unroll
    for (int o = 16; o > 0; o >>= 1) ss += __shfl_xor_sync(0xffffffffu, ss, o);
    __shared__ float ws[8];
    __shared__ float s_inv;
    if ((t & 31) == 0) ws[t >> 5] = ss;
    __syncthreads();
    if (t == 0) {
        float tot = 0.f;
        #pragma unroll
        for (int w = 0; w < 8; w++) tot += ws[w];
        float inv = 1.0f / fmaxf(sqrtf(tot), EPSF);
        s_inv = inv;
        g_inv[row]  = inv;
        g_best[row] = 0ULL;                      // per-replay reset
    }
    __syncthreads();
    float inv = s_inv;
    __nv_bfloat162 b01 = __floats2bfloat162_rn(v.x * inv, v.y * inv);
    __nv_bfloat162 b23 = __floats2bfloat162_rn(v.z * inv, v.w * inv);
    uint2 pk;
    pk.x = *(uint32_t*)&b01; pk.y = *(uint32_t*)&b23;
    ((uint2*)(g_xbf + (size_t)row * DD))[t] = pk;
}

// ---------------- phase 2: HMMA GEMM 128x256 tiles (triangular) + argmax -------
// 8 warps as 2x4: warp = 64 rows x 64 cols.
__global__ __launch_bounds__(256, 1)
void simgemm_mma_kernel() {
    extern __shared__ char dsm[];
    __shared__ unsigned long long rb[TM];
    __shared__ unsigned long long cb[TNC];

    const int bi = blockIdx.y, bj = blockIdx.x;
    if (bi > 2 * bj + 1) return;                 // tile fully below diagonal

    const int t   = threadIdx.x;
    const int wid = t >> 5, lid = t & 31;
    const int wr  = wid >> 2, wc = wid & 3;      // 2 x 4 warp grid

    if (t < TM) rb[t] = 0ULL;
    cb[t] = 0ULL;                                // 256 entries, 1 per thread

    const uint32_t base = smem_u32(dsm);
    const uint32_t Ab[2] = { base,          base + STG_B };
    const uint32_t Bb[2] = { base + ABUF,   base + STG_B + ABUF };

    // per-lane ldmatrix base offsets (bytes), row stride 144
    const int r8 = lid & 7, g4 = lid >> 3;
    const uint32_t aoff = (uint32_t)((wr * 64 + r8 + (g4 & 1) * 8) * 144 + (g4 >> 1) * 16);
    const uint32_t boff = (uint32_t)((wc * 64 + (g4 >> 1) * 8 + r8) * 144 + (g4 & 1) * 16);

    float acc[4][8][4];                          // [mi2][n8][frag]
    #pragma unroll
    for (int i = 0; i < 4; i++)
        #pragma unroll
        for (int j = 0; j < 8; j++)
            #pragma unroll
            for (int r = 0; r < 4; r++) acc[i][j][r] = 0.f;

    const char* xb = (const char*)g_xbf;         // row stride 2048 B
    const size_t arow0 = (size_t)bi * TM, brow0 = (size_t)bj * TNC;

    // 3072 16B-chunks per stage (A: 1024, B: 2048); 12 per thread
    auto issue = [&](int s, int p) {
        #pragma unroll
        for (int i = 0; i < 12; i++) {
            int q = t + i * 256;
            bool isB = q >= 1024;
            int qq = isB ? q - 1024 : q;
            int r = qq >> 3, c = qq & 7;
            uint32_t dst = (isB ? Bb[p] : Ab[p]) + (uint32_t)(r * 144 + c * 16);
            const char* src = xb + ((isB ? brow0 : arow0) + r) * 2048 + s * 128 + c * 16;
            cpasync16(dst, src);
        }
        asm volatile("cp.async.commit_group;" ::: "memory");
    };

    issue(0, 0);
    for (int s = 0; s < NSTG; s++) {
        int p = s & 1;
        if (s + 1 < NSTG) {
            issue(s + 1, (s + 1) & 1);
            asm volatile("cp.async.wait_group 1;" ::: "memory");
        } else {
            asm volatile("cp.async.wait_group 0;" ::: "memory");
        }
        __syncthreads();

        #pragma unroll
        for (int kf = 0; kf < 4; kf++) {         // four k16 frags per stage
            uint32_t a[4][4];
            #pragma unroll
            for (int mi2 = 0; mi2 < 4; mi2++)
                ldsm_x4(a[mi2], Ab[p] + aoff + (uint32_t)(mi2 * 16 * 144 + kf * 32));
            #pragma unroll
            for (int np = 0; np < 4; np++) {
                uint32_t b[4];
                ldsm_x4(b, Bb[p] + boff + (uint32_t)(np * 16 * 144 + kf * 32));
                #pragma unroll
                for (int mi2 = 0; mi2 < 4; mi2++) {
                    mma16816(acc[mi2][np * 2 + 0], a[mi2], b[0], b[1]);
                    mma16816(acc[mi2][np * 2 + 1], a[mi2], b[2], b[3]);
                }
            }
        }
        __syncthreads();                         // protect buf p before reissue
    }

    // ---- epilogue: row-side + col-side argmax over the 128x256 tile ----
    const int rloc0 = wr * 64 + (lid >> 2);      // + mi2*16 + rh*8
    const int cloc0 = wc * 64 + (lid & 3) * 2;   // + n8*8 + c01 (within n8 pair step)
    const int ibase = bi * TM, jbase = bj * TNC;

    // row side: 8 rows per thread, max over 16 cols held
    #pragma unroll
    for (int mi2 = 0; mi2 < 4; mi2++)
        #pragma unroll
        for (int rh = 0; rh < 2; rh++) {
            int rloc = rloc0 + mi2 * 16 + rh * 8;
            int rowg = ibase + rloc;
            float m = -2.0f; int mj = 0;
            #pragma unroll
            for (int n8 = 0; n8 < 8; n8++)
                #pragma unroll
                for (int c01 = 0; c01 < 2; c01++) {
                    int colg = jbase + cloc0 + n8 * 8 + c01;
                    float v = acc[mi2][n8][rh * 2 + c01];
                    if (colg == rowg) v = -2.0f;     // mask self
                    if (v > m) { m = v; mj = colg; }
                }
            atomicMax(&rb[rloc], packkey(m, mj));
        }
    // col side: 16 cols per thread, max over 8 rows held
    #pragma unroll
    for (int n8 = 0; n8 < 8; n8++)
        #pragma unroll
        for (int c01 = 0; c01 < 2; c01++) {
            int cloc = cloc0 + n8 * 8 + c01;
            int colg = jbase + cloc;
            float m = -2.0f; int mi = 0;
            #pragma unroll
            for (int mi2 = 0; mi2 < 4; mi2++)
                #pragma unroll
                for (int rh = 0; rh < 2; rh++) {
                    int rowg = ibase + rloc0 + mi2 * 16 + rh * 8;
                    float v = acc[mi2][n8][rh * 2 + c01];
                    if (rowg == colg) v = -2.0f;     // mask self
                    if (v > m) { m = v; mi = rowg; }
                }
            atomicMax(&cb[cloc], packkey(m, mi));
        }
    __syncthreads();
    if (t < TM) atomicMax(&g_best[ibase + t], rb[t]);
    atomicMax(&g_best[jbase + t], cb[t]);
}

// ---------------- phase 3: exact fp32 distance + log ---------------------------
__global__ void dist_log_kernel(const float* __restrict__ x) {
    int i = blockIdx.x;
    int t = threadIdx.x;
    int j = (int)(unsigned)(g_best[i] & 0xffffffffULL);
    float ia = g_inv[i], ib = g_inv[j];
    float4 a = ((const float4*)(x + (size_t)i * DD))[t];
    float4 b = ((const float4*)(x + (size_t)j * DD))[t];
    float dx = a.x*ia - b.x*ib + EPSF, dy = a.y*ia - b.y*ib + EPSF;
    float dz = a.z*ia - b.z*ib + EPSF, dw = a.w*ia - b.w*ib + EPSF;
    float ss = dx*dx + dy*dy + dz*dz + dw*dw;
    #pragma unroll
    for (int o = 16; o > 0; o >>= 1) ss += __shfl_xor_sync(0xffffffffu, ss, o);
    __shared__ float ws[8];
    if ((t & 31) == 0) ws[t >> 5] = ss;
    __syncthreads();
    if (t == 0) {
        float tot = 0.f;
        #pragma unroll
        for (int w = 0; w < 8; w++) tot += ws[w];
        g_logs[i] = logf(sqrtf(tot) + EPSF);
    }
}

// ---------------- phase 4: deterministic mean ----------------------------------
__global__ void final_kernel(float* __restrict__ out) {
    int t = threadIdx.x;
    double s = 0.0;
    for (int q = t; q < NB; q += 256) s += (double)g_logs[q];
    __shared__ double sh[256];
    sh[t] = s;
    __syncthreads();
    for (int o = 128; o > 0; o >>= 1) {
        if (t < o) sh[t] += sh[t + o];
        __syncthreads();
    }
    if (t == 0) out[0] = (float)(-sh[0] / (double)NB);
}

// ---------------- launch -------------------------------------------------------
extern "C" void kernel_launch(void* const* d_in, const int* in_sizes, int n_in,
                              void* d_out, int out_size) {
    (void)in_sizes; (void)n_in; (void)out_size;
    const float* x = (const float*)d_in[0];

    cudaFuncSetAttribute(simgemm_mma_kernel,
                         cudaFuncAttributeMaxDynamicSharedMemorySize, SMEM_DYN);

    normalize_kernel<<<NB, 256>>>(x);
    dim3 grid(NB / TNC, NB / TM);                // 64 x 128, upper-ish triangle
    simgemm_mma_kernel<<<grid, 256, SMEM_DYN>>>();
    dist_log_kernel<<<NB, 256>>>(x);
    final_kernel<<<1, 256>>>((float*)d_out);
}

// round 14
// speedup vs baseline: 1.6662x; 1.6662x over previous
#include <cuda_runtime.h>
#include <cuda_bf16.h>
#include <cstdint>

#define NB    16384
#define DD    1024
#define EPSF  1e-8f
#define TILE  128
#define KCH   32                      // k elems per stage
#define NSTG  (DD / KCH)              // 32 stages
#define LDS_  40                      // smem row stride in bf16 (80 B, 16B-aligned)
#define ABUF  (TILE * LDS_ * 2)       // 10240 B per A stage
#define STG_B (2 * ABUF)              // A + B per stage = 20480 B
#define SMEM_DYN (3 * STG_B)          // 61440 B, 3-stage ring

// ---------------- device scratch (allocation-free rule) ------------------------
__device__ float               g_xn[(size_t)NB * DD];    // 64 MB fp32 normalized
__device__ __nv_bfloat16       g_xbf[(size_t)NB * DD];   // 32 MB bf16 normalized
__device__ unsigned long long  g_best[NB];
__device__ float               g_logs[NB];

// ---------------- helpers ------------------------------------------------------
__device__ __forceinline__ uint32_t smem_u32(const void* p) {
    uint32_t a;
    asm("{ .reg .u64 t; cvta.to.shared.u64 t, %1; cvt.u32.u64 %0, t; }" : "=r"(a) : "l"(p));
    return a;
}
__device__ __forceinline__ unsigned long long packkey(float v, int j) {
    unsigned u = __float_as_uint(v);
    u = (u & 0x80000000u) ? ~u : (u | 0x80000000u);   // total order on floats
    return ((unsigned long long)u << 32) | (unsigned)j;
}
__device__ __forceinline__ void cpasync16(uint32_t dst, const void* src) {
    asm volatile("cp.async.cg.shared.global [%0], [%1], 16;" :: "r"(dst), "l"(src) : "memory");
}
__device__ __forceinline__ void ldsm_x4(uint32_t* r, uint32_t addr) {
    asm volatile("ldmatrix.sync.aligned.m8n8.x4.shared.b16 {%0,%1,%2,%3}, [%4];"
                 : "=r"(r[0]), "=r"(r[1]), "=r"(r[2]), "=r"(r[3]) : "r"(addr));
}
__device__ __forceinline__ void mma16816(float* c, const uint32_t* a, uint32_t b0, uint32_t b1) {
    asm volatile("mma.sync.aligned.m16n8k16.row.col.f32.bf16.bf16.f32 "
                 "{%0,%1,%2,%3}, {%4,%5,%6,%7}, {%8,%9}, {%0,%1,%2,%3};"
                 : "+f"(c[0]), "+f"(c[1]), "+f"(c[2]), "+f"(c[3])
                 : "r"(a[0]), "r"(a[1]), "r"(a[2]), "r"(a[3]), "r"(b0), "r"(b1));
}

// ---------------- phase 1: normalize -> fp32 + bf16, reset g_best --------------
__global__ void normalize_kernel(const float* __restrict__ x) {
    int row = blockIdx.x;
    int t   = threadIdx.x;                       // 256 threads, 1 float4 each
    float4 v = ((const float4*)(x + (size_t)row * DD))[t];
    float ss = v.x*v.x + v.y*v.y + v.z*v.z + v.w*v.w;
    #pragma unroll
    for (int o = 16; o > 0; o >>= 1) ss += __shfl_xor_sync(0xffffffffu, ss, o);
    __shared__ float ws[8];
    __shared__ float s_inv;
    if ((t & 31) == 0) ws[t >> 5] = ss;
    __syncthreads();
    if (t == 0) {
        float tot = 0.f;
        #pragma unroll
        for (int w = 0; w < 8; w++) tot += ws[w];
        s_inv = 1.0f / fmaxf(sqrtf(tot), EPSF);
        g_best[row] = 0ULL;                      // per-replay reset
    }
    __syncthreads();
    float inv = s_inv;
    float4 o = make_float4(v.x*inv, v.y*inv, v.z*inv, v.w*inv);
    ((float4*)(g_xn + (size_t)row * DD))[t] = o;
    __nv_bfloat162 b01 = __floats2bfloat162_rn(o.x, o.y);
    __nv_bfloat162 b23 = __floats2bfloat162_rn(o.z, o.w);
    uint2 pk;
    pk.x = *(uint32_t*)&b01; pk.y = *(uint32_t*)&b23;
    ((uint2*)(g_xbf + (size_t)row * DD))[t] = pk;
}

// ---------------- phase 2: HMMA GEMM (triangular) + fused argmax ---------------
// 8 warps as 2x4: warp covers rows [wr*64,+64) x cols [wc*32,+32) of 128x128 tile.
// 3-stage cp.async ring, ONE __syncthreads per stage.
__global__ __launch_bounds__(256, 2)
void simgemm_mma_kernel() {
    extern __shared__ char dsm[];
    __shared__ unsigned long long  rb[TILE];
    __shared__ unsigned long long  cb[TILE];

    const int bi = blockIdx.y, bj = blockIdx.x;
    if (bj < bi) return;
    const bool diag = (bi == bj);

    const int t   = threadIdx.x;
    const int wid = t >> 5, lid = t & 31;
    const int wr  = wid >> 2, wc = wid & 3;      // 2 x 4 warp grid

    if (t < TILE) { rb[t] = 0ULL; cb[t] = 0ULL; }

    const uint32_t base = smem_u32(dsm);
    // stage p: A at base + p*STG_B, B at base + p*STG_B + ABUF

    // per-lane ldmatrix base offsets (bytes), row stride 80
    const int r8 = lid & 7, g4 = lid >> 3;
    const uint32_t aoff = (uint32_t)((wr * 64 + r8 + (g4 & 1) * 8) * (LDS_ * 2) + (g4 >> 1) * 16);
    const uint32_t boff = (uint32_t)((wc * 32 + (g4 >> 1) * 8 + r8) * (LDS_ * 2) + (g4 & 1) * 16);

    float acc[4][4][4];                          // [mi2][ni2][frag]
    #pragma unroll
    for (int i = 0; i < 4; i++)
        #pragma unroll
        for (int j = 0; j < 4; j++)
            #pragma unroll
            for (int r = 0; r < 4; r++) acc[i][j][r] = 0.f;

    const char* xb = (const char*)g_xbf;         // row stride 2048 B
    const size_t arow0 = (size_t)bi * TILE, brow0 = (size_t)bj * TILE;

    // 1024 16B-chunks per stage (A: 512, B: 512); 4 per thread
    auto issue = [&](int s, int p) {
        uint32_t Ab = base + (uint32_t)p * STG_B;
        uint32_t Bb = Ab + ABUF;
        #pragma unroll
        for (int i = 0; i < 4; i++) {
            int q = t + i * 256;
            int isB = q >> 9;                    // 0: A, 1: B
            int qq = q & 511;
            int r = qq >> 2, c = qq & 3;
            uint32_t dst = (isB ? Bb : Ab) + (uint32_t)(r * (LDS_ * 2) + c * 16);
            const char* src = xb + ((isB ? brow0 : arow0) + r) * 2048 + s * 64 + c * 16;
            cpasync16(dst, src);
        }
        asm volatile("cp.async.commit_group;" ::: "memory");
    };

    issue(0, 0);
    issue(1, 1);
    int p = 0;
    for (int s = 0; s < NSTG; s++) {
        if (s + 1 < NSTG) {
            asm volatile("cp.async.wait_group 1;" ::: "memory");
        } else {
            asm volatile("cp.async.wait_group 0;" ::: "memory");
        }
        __syncthreads();                         // stage s ready; all iter s-1 reads done
        if (s + 2 < NSTG) issue(s + 2, (p + 2) % 3);

        uint32_t Ab = base + (uint32_t)p * STG_B;
        uint32_t Bb = Ab + ABUF;
        #pragma unroll
        for (int kf = 0; kf < 2; kf++) {         // two k16 frags per stage
            uint32_t a[4][4];
            #pragma unroll
            for (int mi2 = 0; mi2 < 4; mi2++)
                ldsm_x4(a[mi2], Ab + aoff + (uint32_t)(mi2 * 16 * (LDS_ * 2) + kf * 32));
            #pragma unroll
            for (int np = 0; np < 2; np++) {
                uint32_t b[4];
                ldsm_x4(b, Bb + boff + (uint32_t)(np * 16 * (LDS_ * 2) + kf * 32));
                #pragma unroll
                for (int mi2 = 0; mi2 < 4; mi2++) {
                    mma16816(acc[mi2][np * 2 + 0], a[mi2], b[0], b[1]);
                    mma16816(acc[mi2][np * 2 + 1], a[mi2], b[2], b[3]);
                }
            }
        }
        p = (p + 1) % 3;
    }

    // ---- epilogue: row-side + col-side argmax over the 128x128 tile ----
    const int rloc0 = wr * 64 + (lid >> 2);      // + mi2*16 + rh*8
    const int cloc0 = wc * 32 + (lid & 3) * 2;   // + ni2*8 + c01
    const int ibase = bi * TILE, jbase = bj * TILE;

    // row side: 8 rows per thread, max over 8 cols held
    #pragma unroll
    for (int mi2 = 0; mi2 < 4; mi2++)
        #pragma unroll
        for (int rh = 0; rh < 2; rh++) {
            int rloc = rloc0 + mi2 * 16 + rh * 8;
            int rowg = ibase + rloc;
            float m = -2.0f; int mj = 0;
            #pragma unroll
            for (int ni2 = 0; ni2 < 4; ni2++)
                #pragma unroll
                for (int c01 = 0; c01 < 2; c01++) {
                    int colg = jbase + cloc0 + ni2 * 8 + c01;
                    float v = acc[mi2][ni2][rh * 2 + c01];
                    if (diag && colg == rowg) v = -2.0f;
                    if (v > m) { m = v; mj = colg; }
                }
            atomicMax(&rb[rloc], packkey(m, mj));
        }
    // col side: 8 cols per thread, max over 8 rows held
    if (!diag) {
        #pragma unroll
        for (int ni2 = 0; ni2 < 4; ni2++)
            #pragma unroll
            for (int c01 = 0; c01 < 2; c01++) {
                int cloc = cloc0 + ni2 * 8 + c01;
                float m = -2.0f; int mi = 0;
                #pragma unroll
                for (int mi2 = 0; mi2 < 4; mi2++)
                    #pragma unroll
                    for (int rh = 0; rh < 2; rh++) {
                        float v = acc[mi2][ni2][rh * 2 + c01];
                        int rowg = ibase + rloc0 + mi2 * 16 + rh * 8;
                        if (v > m) { m = v; mi = rowg; }
                    }
                atomicMax(&cb[cloc], packkey(m, mi));
            }
    }
    __syncthreads();
    if (t < TILE) {
        atomicMax(&g_best[ibase + t], rb[t]);
        if (!diag) atomicMax(&g_best[jbase + t], cb[t]);
    }
}

// ---------------- phase 3: exact fp32 distance + log ---------------------------
__global__ void dist_log_kernel() {
    int i = blockIdx.x;
    int t = threadIdx.x;
    int j = (int)(unsigned)(g_best[i] & 0xffffffffULL);
    float4 a = ((const float4*)(g_xn + (size_t)i * DD))[t];
    float4 b = ((const float4*)(g_xn + (size_t)j * DD))[t];
    float dx = a.x - b.x + EPSF, dy = a.y - b.y + EPSF;
    float dz = a.z - b.z + EPSF, dw = a.w - b.w + EPSF;
    float ss = dx*dx + dy*dy + dz*dz + dw*dw;
    #pragma unroll
    for (int o = 16; o > 0; o >>= 1) ss += __shfl_xor_sync(0xffffffffu, ss, o);
    __shared__ float ws[8];
    if ((t & 31) == 0) ws[t >> 5] = ss;
    __syncthreads();
    if (t == 0) {
        float tot = 0.f;
        #pragma unroll
        for (int w = 0; w < 8; w++) tot += ws[w];
        g_logs[i] = logf(sqrtf(tot) + EPSF);
    }
}

// ---------------- phase 4: deterministic mean ----------------------------------
__global__ void final_kernel(float* __restrict__ out) {
    int t = threadIdx.x;
    double s = 0.0;
    for (int q = t; q < NB; q += 256) s += (double)g_logs[q];
    __shared__ double sh[256];
    sh[t] = s;
    __syncthreads();
    for (int o = 128; o > 0; o >>= 1) {
        if (t < o) sh[t] += sh[t + o];
        __syncthreads();
    }
    if (t == 0) out[0] = (float)(-sh[0] / (double)NB);
}

// ---------------- launch -------------------------------------------------------
extern "C" void kernel_launch(void* const* d_in, const int* in_sizes, int n_in,
                              void* d_out, int out_size) {
    (void)in_sizes; (void)n_in; (void)out_size;
    const float* x = (const float*)d_in[0];

    cudaFuncSetAttribute(simgemm_mma_kernel,
                         cudaFuncAttributeMaxDynamicSharedMemorySize, SMEM_DYN);

    normalize_kernel<<<NB, 256>>>(x);
    dim3 grid(NB / TILE, NB / TILE);             // 128 x 128, upper triangle active
    simgemm_mma_kernel<<<grid, 256, SMEM_DYN>>>();
    dist_log_kernel<<<NB, 256>>>();
    final_kernel<<<1, 256>>>((float*)d_out);
}